// round 6
// baseline (speedup 1.0000x reference)
#include <cuda_runtime.h>
#include <cuda_bf16.h>
#include <cstdint>

// LocallyConnected2d via mma.sync (bf16 hi/lo 3-pass, fp32 accum).
// One CTA per (h,w): D[64b x 64o] = A[64 x 576] * B[576 x 64], K=(ci,kh,kw).
// Operands K-major in smem ([k][row], stride 144B = 9x16B -> conflict-free
// ldmatrix.x4.trans and coalesced STS). K chunks of 8 ci (72 k, pad to 80),
// double-buffered. 4 warps in 2x2 (M32 x N32 each), 2 CTAs/SM.

#define VSTRIDE 11520                 // one operand version: 80 rows x 144 B
#define DYN_SMEM (512 + 8 * VSTRIDE)  // bias + {AH,AL,BH,BL} x 2 buffers

static __device__ __forceinline__ uint32_t s2u(const void* p) {
    uint32_t a;
    asm("{ .reg .u64 t; cvta.to.shared.u64 t, %1; cvt.u32.u64 %0, t; }"
        : "=r"(a) : "l"(p));
    return a;
}

static __device__ __forceinline__ void ldsm4t(uint32_t addr, uint32_t* r) {
    asm volatile("ldmatrix.sync.aligned.m8n8.x4.trans.shared.b16 {%0,%1,%2,%3}, [%4];"
                 : "=r"(r[0]), "=r"(r[1]), "=r"(r[2]), "=r"(r[3]) : "r"(addr));
}

static __device__ __forceinline__ void mma_bf16(float* d, const uint32_t* a,
                                                const uint32_t* b) {
    asm volatile("mma.sync.aligned.m16n8k16.row.col.f32.bf16.bf16.f32 "
                 "{%0,%1,%2,%3}, {%4,%5,%6,%7}, {%8,%9}, {%0,%1,%2,%3};"
                 : "+f"(d[0]), "+f"(d[1]), "+f"(d[2]), "+f"(d[3])
                 : "r"(a[0]), "r"(a[1]), "r"(a[2]), "r"(a[3]),
                   "r"(b[0]), "r"(b[1]));
}

// Stage one 8-ci chunk into buffer `buf`: warps 0-1 stage A (x patches, b=tid),
// warps 2-3 stage B (weights, o=tid-64). Lanes sweep b/o -> coalesced STS.
static __device__ void stage_chunk(char* sm, int buf, int chunk, int tid,
                                   const float* __restrict__ x,
                                   const float* __restrict__ wgt, int h, int w)
{
    const int r64 = tid & 63;
    char* vb = sm + 512 + buf * 4 * VSTRIDE;
    if (tid < 64) {
        const int b = r64;
        char* ph = vb;                // A hi
        char* pl = vb + VSTRIDE;      // A lo
        const float* xb = x + (size_t)b * 65536 + (size_t)chunk * 8192;
        #pragma unroll
        for (int ci_l = 0; ci_l < 8; ci_l++) {
            const float* xc = xb + ci_l * 1024;
            #pragma unroll
            for (int kh = 0; kh < 3; kh++) {
                const int r = h - 1 + kh;
                const bool rok = (unsigned)r < 32u;
                #pragma unroll
                for (int kw = 0; kw < 3; kw++) {
                    const int c = w - 1 + kw;
                    float v = (rok && (unsigned)c < 32u) ? xc[r * 32 + c] : 0.f;
                    __nv_bfloat16 hi = __float2bfloat16(v);
                    __nv_bfloat16 lo = __float2bfloat16(v - __bfloat162float(hi));
                    const int k = ci_l * 9 + kh * 3 + kw;
                    *(__nv_bfloat16*)(ph + k * 144 + b * 2) = hi;
                    *(__nv_bfloat16*)(pl + k * 144 + b * 2) = lo;
                }
            }
        }
    } else {
        const int o = r64;
        char* ph = vb + 2 * VSTRIDE;  // B hi
        char* pl = vb + 3 * VSTRIDE;  // B lo
        #pragma unroll
        for (int ci_l = 0; ci_l < 8; ci_l++) {
            const int ci = chunk * 8 + ci_l;
            const float* wr = wgt + ((size_t)(ci * 64 + o) * 1024 + h * 32 + w) * 9;
            #pragma unroll
            for (int kk = 0; kk < 9; kk++) {
                float v = wr[kk];
                __nv_bfloat16 hi = __float2bfloat16(v);
                __nv_bfloat16 lo = __float2bfloat16(v - __bfloat162float(hi));
                const int k = ci_l * 9 + kk;
                *(__nv_bfloat16*)(ph + k * 144 + o * 2) = hi;
                *(__nv_bfloat16*)(pl + k * 144 + o * 2) = lo;
            }
        }
    }
}

__global__ __launch_bounds__(128, 2)
void lc2d_mma_kernel(const float* __restrict__ x, const float* __restrict__ wgt,
                     const float* __restrict__ bias, float* __restrict__ out)
{
    extern __shared__ char sm[];
    const uint32_t sb = s2u(sm);
    const int tid  = threadIdx.x;
    const int wid  = tid >> 5;
    const int lane = tid & 31;
    const int h = blockIdx.x >> 5;
    const int w = blockIdx.x & 31;

    float* biasS = (float*)sm;
    if (tid < 64) biasS[tid] = bias[tid * 1024 + h * 32 + w];

    // Zero pad rows k=72..79 of all 8 operand versions (read by k-step 4, never restaged).
    for (int q = tid; q < 2304; q += 128) {
        const int vi = q / 288, rr = q % 288;
        *(float*)(sm + 512 + vi * VSTRIDE + (72 + rr / 36) * 144 + (rr % 36) * 4) = 0.f;
    }

    // ldmatrix.x4.trans lane geometry.
    // A blocks: (k0,m0)(k0,m8)(k8,m0)(k8,m8) -> a0..a3 of m16n8k16 row-A.
    // B blocks: (k0,n0)(k8,n0)(k0,n8)(k8,n8) -> {b0,b1} for 2 n8 tiles.
    const int blk = lane >> 3, rin = lane & 7;
    const uint32_t aoff = (uint32_t)(((blk >> 1) * 8 + rin) * 144 + ((blk & 1) * 8) * 2);
    const uint32_t boff = (uint32_t)(((blk & 1) * 8 + rin) * 144 + ((blk >> 1) * 8) * 2);
    const int wm = (wid >> 1) * 32;   // warp M base
    const int wn = (wid & 1) * 32;    // warp N base

    float acc[2][4][4];
    #pragma unroll
    for (int i = 0; i < 2; i++)
        #pragma unroll
        for (int j = 0; j < 4; j++)
            #pragma unroll
            for (int k = 0; k < 4; k++)
                acc[i][j][k] = 0.f;

    stage_chunk(sm, 0, 0, tid, x, wgt, h, w);
    __syncthreads();

    for (int c = 0; c < 8; c++) {
        const uint32_t vb = sb + 512 + (uint32_t)(c & 1) * 4 * VSTRIDE;
        const uint32_t AH = vb, AL = vb + VSTRIDE;
        const uint32_t BH = vb + 2 * VSTRIDE, BL = vb + 3 * VSTRIDE;

        #pragma unroll
        for (int ks = 0; ks < 5; ks++) {
            const uint32_t kb = (uint32_t)(ks * 16 * 144);
            uint32_t ah[2][4], al[2][4], bh[2][4], bl[2][4];
            #pragma unroll
            for (int mt = 0; mt < 2; mt++) {
                const uint32_t ad = kb + aoff + (uint32_t)((wm + mt * 16) * 2);
                ldsm4t(AH + ad, ah[mt]);
                ldsm4t(AL + ad, al[mt]);
            }
            #pragma unroll
            for (int p = 0; p < 2; p++) {
                const uint32_t bd = kb + boff + (uint32_t)((wn + p * 16) * 2);
                ldsm4t(BH + bd, bh[p]);
                ldsm4t(BL + bd, bl[p]);
            }
            #pragma unroll
            for (int mt = 0; mt < 2; mt++)
                #pragma unroll
                for (int nt = 0; nt < 4; nt++) {
                    const uint32_t* B2h = &bh[nt >> 1][(nt & 1) * 2];
                    const uint32_t* B2l = &bl[nt >> 1][(nt & 1) * 2];
                    mma_bf16(acc[mt][nt], ah[mt], B2h);   // hi*hi
                    mma_bf16(acc[mt][nt], ah[mt], B2l);   // hi*lo
                    mma_bf16(acc[mt][nt], al[mt], B2h);   // lo*hi
                }
        }
        if (c < 7) stage_chunk(sm, (c & 1) ^ 1, c + 1, tid, x, wgt, h, w);
        __syncthreads();
    }

    // Epilogue: acc frag (c0:(g,2t2) c1:(g,2t2+1) c2:(g+8,2t2) c3:(g+8,2t2+1)).
    const int g = lane >> 2, t2 = lane & 3;
    #pragma unroll
    for (int mt = 0; mt < 2; mt++)
        #pragma unroll
        for (int nt = 0; nt < 4; nt++)
            #pragma unroll
            for (int cc = 0; cc < 4; cc++) {
                const int b = wm + mt * 16 + g + (cc >> 1) * 8;
                const int o = wn + nt * 8 + t2 * 2 + (cc & 1);
                out[((size_t)(b * 64 + o) << 10) + h * 32 + w] =
                    acc[mt][nt][cc] + biasS[o];
            }
}

extern "C" void kernel_launch(void* const* d_in, const int* in_sizes, int n_in,
                              void* d_out, int out_size)
{
    const float* x    = (const float*)d_in[0];
    const float* wgt  = (const float*)d_in[1];
    const float* bias = (const float*)d_in[2];
    float* out        = (float*)d_out;

    cudaFuncSetAttribute(lc2d_mma_kernel,
                         cudaFuncAttributeMaxDynamicSharedMemorySize, DYN_SMEM);
    lc2d_mma_kernel<<<1024, 128, DYN_SMEM>>>(x, wgt, bias, out);
}

// round 8
// speedup vs baseline: 1.0858x; 1.0858x over previous
#include <cuda_runtime.h>
#include <cuda_bf16.h>
#include <cstdint>

// LocallyConnected2d via mma.sync (bf16 hi/lo 3-pass, fp32 accum).
// One CTA per (h,w): D[64b x 64o] = A[64 x 576] * B[576 x 64], K=(ci,kh,kw).
// Round 6: 256 threads (8 warps, 2x4 grid, M32xN16/warp), register-prefetch
// staging (LDGs for chunk c+1 issued before compute of chunk c), double buffer.

#define VSTRIDE 11520                 // one operand version: 80 rows x 144 B
#define DYN_SMEM (512 + 8 * VSTRIDE)  // bias + {AH,AL,BH,BL} x 2 buffers

static __device__ __forceinline__ uint32_t s2u(const void* p) {
    uint32_t a;
    asm("{ .reg .u64 t; cvta.to.shared.u64 t, %1; cvt.u32.u64 %0, t; }"
        : "=r"(a) : "l"(p));
    return a;
}

static __device__ __forceinline__ void ldsm4t(uint32_t addr, uint32_t* r) {
    asm volatile("ldmatrix.sync.aligned.m8n8.x4.trans.shared.b16 {%0,%1,%2,%3}, [%4];"
                 : "=r"(r[0]), "=r"(r[1]), "=r"(r[2]), "=r"(r[3]) : "r"(addr));
}

static __device__ __forceinline__ void mma_bf16(float* d, const uint32_t* a,
                                                const uint32_t* b) {
    asm volatile("mma.sync.aligned.m16n8k16.row.col.f32.bf16.bf16.f32 "
                 "{%0,%1,%2,%3}, {%4,%5,%6,%7}, {%8,%9}, {%0,%1,%2,%3};"
                 : "+f"(d[0]), "+f"(d[1]), "+f"(d[2]), "+f"(d[3])
                 : "r"(a[0]), "r"(a[1]), "r"(a[2]), "r"(a[3]),
                   "r"(b[0]), "r"(b[1]));
}

// ---- staging: threads 0-127 stage A (x patches), 128-255 stage B (weights).
// Each thread covers (row = tid&63, ci-half = 4 ci) -> 36 gmem floats.

static __device__ __forceinline__ void stage_load(float* v, int tid, int chunk,
                                                  const float* __restrict__ x,
                                                  const float* __restrict__ wgt,
                                                  int h, int w)
{
    const int r64  = tid & 63;
    const int half = (tid >> 6) & 1;
    if (tid < 128) {
        const float* xb = x + (size_t)r64 * 65536
                            + (size_t)(chunk * 8 + half * 4) * 1024;
        #pragma unroll
        for (int ci_l = 0; ci_l < 4; ci_l++) {
            const float* xc = xb + ci_l * 1024;
            #pragma unroll
            for (int kh = 0; kh < 3; kh++) {
                const int r = h - 1 + kh;
                const bool rok = (unsigned)r < 32u;
                #pragma unroll
                for (int kw = 0; kw < 3; kw++) {
                    const int c = w - 1 + kw;
                    v[ci_l * 9 + kh * 3 + kw] =
                        (rok && (unsigned)c < 32u) ? xc[r * 32 + c] : 0.f;
                }
            }
        }
    } else {
        #pragma unroll
        for (int ci_l = 0; ci_l < 4; ci_l++) {
            const int ci = chunk * 8 + half * 4 + ci_l;
            const float* wr = wgt + ((size_t)(ci * 64 + r64) * 1024 + h * 32 + w) * 9;
            #pragma unroll
            for (int kk = 0; kk < 9; kk++)
                v[ci_l * 9 + kk] = wr[kk];
        }
    }
}

static __device__ __forceinline__ void stage_store(const float* v, char* sm,
                                                   int buf, int tid)
{
    const int r64  = tid & 63;
    const int half = (tid >> 6) & 1;
    char* vb = sm + 512 + buf * 4 * VSTRIDE + (tid < 128 ? 0 : 2 * VSTRIDE);
    char* ph = vb;
    char* pl = vb + VSTRIDE;
    #pragma unroll
    for (int ci_l = 0; ci_l < 4; ci_l++) {
        #pragma unroll
        for (int kk = 0; kk < 9; kk++) {
            const float f = v[ci_l * 9 + kk];
            __nv_bfloat16 hi = __float2bfloat16(f);
            __nv_bfloat16 lo = __float2bfloat16(f - __bfloat162float(hi));
            const int k = (half * 4 + ci_l) * 9 + kk;
            *(__nv_bfloat16*)(ph + k * 144 + r64 * 2) = hi;
            *(__nv_bfloat16*)(pl + k * 144 + r64 * 2) = lo;
        }
    }
}

__global__ __launch_bounds__(256, 2)
void lc2d_mma_kernel(const float* __restrict__ x, const float* __restrict__ wgt,
                     const float* __restrict__ bias, float* __restrict__ out)
{
    extern __shared__ char sm[];
    const uint32_t sb = s2u(sm);
    const int tid  = threadIdx.x;
    const int wid  = tid >> 5;
    const int lane = tid & 31;
    const int h = blockIdx.x >> 5;
    const int w = blockIdx.x & 31;

    float* biasS = (float*)sm;
    if (tid < 64) biasS[tid] = bias[tid * 1024 + h * 32 + w];

    // Zero pad rows k=72..79 of all 8 operand versions (used by k-step 4 only).
    for (int q = tid; q < 2304; q += 256) {
        const int vi = q / 288, rr = q % 288;
        *(float*)(sm + 512 + vi * VSTRIDE + (72 + rr / 36) * 144 + (rr % 36) * 4) = 0.f;
    }

    // ldmatrix.x4.trans lane geometry (verified round 5).
    const int blk = lane >> 3, rin = lane & 7;
    const uint32_t aoff = (uint32_t)(((blk >> 1) * 8 + rin) * 144 + ((blk & 1) * 8) * 2);
    const uint32_t boff = (uint32_t)(((blk & 1) * 8 + rin) * 144 + ((blk >> 1) * 8) * 2);
    const int wm = (wid >> 2) * 32;   // warp M base (2 rows of warps)
    const int wn = (wid & 3) * 16;    // warp N base (4 cols of warps)

    float acc[2][2][4];
    #pragma unroll
    for (int i = 0; i < 2; i++)
        #pragma unroll
        for (int j = 0; j < 2; j++)
            #pragma unroll
            for (int k = 0; k < 4; k++)
                acc[i][j][k] = 0.f;

    float vbuf[36];
    stage_load(vbuf, tid, 0, x, wgt, h, w);
    stage_store(vbuf, sm, 0, tid);
    __syncthreads();

    for (int c = 0; c < 8; c++) {
        // prefetch next chunk's gmem data into registers (latency hidden by compute)
        if (c < 7) stage_load(vbuf, tid, c + 1, x, wgt, h, w);

        const uint32_t vb = sb + 512 + (uint32_t)(c & 1) * 4 * VSTRIDE;
        const uint32_t AH = vb, AL = vb + VSTRIDE;
        const uint32_t BH = vb + 2 * VSTRIDE, BL = vb + 3 * VSTRIDE;

        #pragma unroll
        for (int ks = 0; ks < 5; ks++) {
            const uint32_t kb = (uint32_t)(ks * 16 * 144);
            uint32_t ah[2][4], al[2][4], bh[4], bl[4];
            #pragma unroll
            for (int mt = 0; mt < 2; mt++) {
                const uint32_t ad = kb + aoff + (uint32_t)((wm + mt * 16) * 2);
                ldsm4t(AH + ad, ah[mt]);
                ldsm4t(AL + ad, al[mt]);
            }
            {
                const uint32_t bd = kb + boff + (uint32_t)(wn * 2);
                ldsm4t(BH + bd, bh);
                ldsm4t(BL + bd, bl);
            }
            #pragma unroll
            for (int mt = 0; mt < 2; mt++)
                #pragma unroll
                for (int nt = 0; nt < 2; nt++) {
                    const uint32_t* B2h = &bh[nt * 2];
                    const uint32_t* B2l = &bl[nt * 2];
                    mma_bf16(acc[mt][nt], ah[mt], B2h);   // hi*hi
                    mma_bf16(acc[mt][nt], ah[mt], B2l);   // hi*lo
                    mma_bf16(acc[mt][nt], al[mt], B2h);   // lo*hi
                }
        }

        if (c < 7) stage_store(vbuf, sm, (c & 1) ^ 1, tid);
        __syncthreads();
    }

    // Epilogue: frag c0:(g,2t2) c1:(g,2t2+1) c2:(g+8,2t2) c3:(g+8,2t2+1).
    const int g = lane >> 2, t2 = lane & 3;
    #pragma unroll
    for (int mt = 0; mt < 2; mt++)
        #pragma unroll
        for (int nt = 0; nt < 2; nt++)
            #pragma unroll
            for (int cc = 0; cc < 4; cc++) {
                const int b = wm + mt * 16 + g + (cc >> 1) * 8;
                const int o = wn + nt * 8 + t2 * 2 + (cc & 1);
                out[((size_t)(b * 64 + o) << 10) + h * 32 + w] =
                    acc[mt][nt][cc] + biasS[o];
            }
}

extern "C" void kernel_launch(void* const* d_in, const int* in_sizes, int n_in,
                              void* d_out, int out_size)
{
    const float* x    = (const float*)d_in[0];
    const float* wgt  = (const float*)d_in[1];
    const float* bias = (const float*)d_in[2];
    float* out        = (float*)d_out;

    cudaFuncSetAttribute(lc2d_mma_kernel,
                         cudaFuncAttributeMaxDynamicSharedMemorySize, DYN_SMEM);
    lc2d_mma_kernel<<<1024, 256, DYN_SMEM>>>(x, wgt, bias, out);
}

// round 9
// speedup vs baseline: 1.8601x; 1.7131x over previous
#include <cuda_runtime.h>
#include <cuda_bf16.h>
#include <cstdint>

// LocallyConnected2d via mma.sync (bf16 hi/lo 3-pass, fp32 accum).
// One CTA per (h,w): D[64b x 64o] = A[64 x 576] * B[576 x 64], K=(ci,kh,kw).
// Round 7: staging remapped for LDG coalescing.
//   Weights: lanes -> (o-triple x kk) ride the contiguous 9-float gmem runs.
//   x:       lanes -> (ci-triple x patch-elem) for fixed b (9 lines vs 32).
// Compute path (ldmatrix/mma geometry, [k][row] 144B layout) identical to R5/6.

#define VSTRIDE 11520                 // one operand version: 80 rows x 144 B
#define DYN_SMEM (512 + 8 * VSTRIDE)  // bias + {AH,AL,BH,BL} x 2 buffers

static __device__ __forceinline__ uint32_t s2u(const void* p) {
    uint32_t a;
    asm("{ .reg .u64 t; cvta.to.shared.u64 t, %1; cvt.u32.u64 %0, t; }"
        : "=r"(a) : "l"(p));
    return a;
}

static __device__ __forceinline__ void ldsm4t(uint32_t addr, uint32_t* r) {
    asm volatile("ldmatrix.sync.aligned.m8n8.x4.trans.shared.b16 {%0,%1,%2,%3}, [%4];"
                 : "=r"(r[0]), "=r"(r[1]), "=r"(r[2]), "=r"(r[3]) : "r"(addr));
}

static __device__ __forceinline__ void mma_bf16(float* d, const uint32_t* a,
                                                const uint32_t* b) {
    asm volatile("mma.sync.aligned.m16n8k16.row.col.f32.bf16.bf16.f32 "
                 "{%0,%1,%2,%3}, {%4,%5,%6,%7}, {%8,%9}, {%0,%1,%2,%3};"
                 : "+f"(d[0]), "+f"(d[1]), "+f"(d[2]), "+f"(d[3])
                 : "r"(a[0]), "r"(a[1]), "r"(a[2]), "r"(a[3]),
                   "r"(b[0]), "r"(b[1]));
}

__global__ __launch_bounds__(256, 2)
void lc2d_mma_kernel(const float* __restrict__ x, const float* __restrict__ wgt,
                     const float* __restrict__ bias, float* __restrict__ out)
{
    extern __shared__ char sm[];
    const uint32_t sb = s2u(sm);
    const int tid  = threadIdx.x;
    const int wid  = tid >> 5;
    const int lane = tid & 31;
    const int h = blockIdx.x >> 5;
    const int w = blockIdx.x & 31;
    const int loc = h * 32 + w;

    float* biasS = (float*)sm;
    if (tid < 64) biasS[tid] = bias[tid * 1024 + loc];

    // Zero pad rows k=72..79 of all 8 operand versions (used by k-step 4 only).
    for (int q = tid; q < 2304; q += 256) {
        const int vi = q / 288, rr = q % 288;
        *(float*)(sm + 512 + vi * VSTRIDE + (72 + rr / 36) * 144 + (rr % 36) * 4) = 0.f;
    }

    // ---- staging roles ----
    const int side = tid >> 7;        // 0: A (x patches), 1: B (weights)
    const int sw   = wid & 3;         // warp within side
    const int lq   = lane / 9;        // sub-group 0..3
    const int le   = lane % 9;        // element within 9-run
    const int kh   = le / 3, kw = le % 3;
    const int xr   = h - 1 + kh, xc = w - 1 + kw;
    const bool xok = ((unsigned)xr < 32u) && ((unsigned)xc < 32u);

    // ldmatrix.x4.trans lane geometry (verified R5/R6).
    const int blk = lane >> 3, rin = lane & 7;
    const uint32_t aoff = (uint32_t)(((blk >> 1) * 8 + rin) * 144 + ((blk & 1) * 8) * 2);
    const uint32_t boff = (uint32_t)(((blk & 1) * 8 + rin) * 144 + ((blk >> 1) * 8) * 2);
    const int wm = (wid >> 2) * 32;   // warp M base
    const int wn = (wid & 3) * 16;    // warp N base

    float acc[2][2][4];
    #pragma unroll
    for (int i = 0; i < 2; i++)
        #pragma unroll
        for (int j = 0; j < 2; j++)
            #pragma unroll
            for (int k = 0; k < 4; k++)
                acc[i][j][k] = 0.f;

    // ---- staging: coalesced-run mappings ----
    auto stage = [&](int chunk, int buf) {
        char* vb = sm + 512 + buf * 4 * VSTRIDE;
        if (side == 0) {
            // A: warp covers b in [sw*16, sw*16+16); lanes = (ci-triple, patch elem)
            char* ph = vb;
            char* pl = vb + VSTRIDE;
            #pragma unroll 4
            for (int bb = 0; bb < 16; bb++) {
                const int b = sw * 16 + bb;
                const float* xb = x + (size_t)b * 65536 + (size_t)chunk * 8192
                                    + xr * 32 + xc;
                float v[3];
                #pragma unroll
                for (int cg = 0; cg < 3; cg++) {
                    const int nact = (cg < 2) ? 27 : 18;
                    v[cg] = 0.f;
                    if (lane < nact && xok)
                        v[cg] = xb[(size_t)(cg * 3 + lq) * 1024];
                }
                #pragma unroll
                for (int cg = 0; cg < 3; cg++) {
                    const int nact = (cg < 2) ? 27 : 18;
                    __nv_bfloat16 hi = __float2bfloat16(v[cg]);
                    __nv_bfloat16 lo = __float2bfloat16(v[cg] - __bfloat162float(hi));
                    if (lane < nact) {
                        const int k = (cg * 3 + lq) * 9 + le;
                        *(__nv_bfloat16*)(ph + k * 144 + b * 2) = hi;
                        *(__nv_bfloat16*)(pl + k * 144 + b * 2) = lo;
                    }
                }
            }
        } else {
            // B: warp covers o in [sw*16, +16); lanes = (o-triple, kk) riding 9-float runs
            char* ph = vb + 2 * VSTRIDE;
            char* pl = vb + 3 * VSTRIDE;
            #pragma unroll 2
            for (int ci_l = 0; ci_l < 8; ci_l++) {
                const int ci = chunk * 8 + ci_l;
                const float* wb = wgt + (size_t)ci * 589824 + (size_t)loc * 9 + le;
                float v[6];
                #pragma unroll
                for (int og = 0; og < 6; og++) {
                    const int nact = (og < 5) ? 27 : 9;
                    v[og] = 0.f;
                    if (lane < nact)
                        v[og] = wb[(size_t)(sw * 16 + og * 3 + lq) * 9216];
                }
                #pragma unroll
                for (int og = 0; og < 6; og++) {
                    const int nact = (og < 5) ? 27 : 9;
                    __nv_bfloat16 hi = __float2bfloat16(v[og]);
                    __nv_bfloat16 lo = __float2bfloat16(v[og] - __bfloat162float(hi));
                    if (lane < nact) {
                        const int o = sw * 16 + og * 3 + lq;
                        const int k = ci_l * 9 + le;
                        *(__nv_bfloat16*)(ph + k * 144 + o * 2) = hi;
                        *(__nv_bfloat16*)(pl + k * 144 + o * 2) = lo;
                    }
                }
            }
        }
    };

    stage(0, 0);
    __syncthreads();

    for (int c = 0; c < 8; c++) {
        if (c < 7) stage(c + 1, (c + 1) & 1);   // fills the other buffer

        const uint32_t vb = sb + 512 + (uint32_t)(c & 1) * 4 * VSTRIDE;
        const uint32_t AH = vb, AL = vb + VSTRIDE;
        const uint32_t BH = vb + 2 * VSTRIDE, BL = vb + 3 * VSTRIDE;

        #pragma unroll
        for (int ks = 0; ks < 5; ks++) {
            const uint32_t kb = (uint32_t)(ks * 16 * 144);
            uint32_t ah[2][4], al[2][4], bh[4], bl[4];
            #pragma unroll
            for (int mt = 0; mt < 2; mt++) {
                const uint32_t ad = kb + aoff + (uint32_t)((wm + mt * 16) * 2);
                ldsm4t(AH + ad, ah[mt]);
                ldsm4t(AL + ad, al[mt]);
            }
            {
                const uint32_t bd = kb + boff + (uint32_t)(wn * 2);
                ldsm4t(BH + bd, bh);
                ldsm4t(BL + bd, bl);
            }
            #pragma unroll
            for (int mt = 0; mt < 2; mt++)
                #pragma unroll
                for (int nt = 0; nt < 2; nt++) {
                    const uint32_t* B2h = &bh[nt * 2];
                    const uint32_t* B2l = &bl[nt * 2];
                    mma_bf16(acc[mt][nt], ah[mt], B2h);   // hi*hi
                    mma_bf16(acc[mt][nt], ah[mt], B2l);   // hi*lo
                    mma_bf16(acc[mt][nt], al[mt], B2h);   // lo*hi
                }
        }
        __syncthreads();
    }

    // Epilogue: frag c0:(g,2t2) c1:(g,2t2+1) c2:(g+8,2t2) c3:(g+8,2t2+1).
    const int g = lane >> 2, t2 = lane & 3;
    #pragma unroll
    for (int mt = 0; mt < 2; mt++)
        #pragma unroll
        for (int nt = 0; nt < 2; nt++)
            #pragma unroll
            for (int cc = 0; cc < 4; cc++) {
                const int b = wm + mt * 16 + g + (cc >> 1) * 8;
                const int o = wn + nt * 8 + t2 * 2 + (cc & 1);
                out[((size_t)(b * 64 + o) << 10) + loc] =
                    acc[mt][nt][cc] + biasS[o];
            }
}

extern "C" void kernel_launch(void* const* d_in, const int* in_sizes, int n_in,
                              void* d_out, int out_size)
{
    const float* x    = (const float*)d_in[0];
    const float* wgt  = (const float*)d_in[1];
    const float* bias = (const float*)d_in[2];
    float* out        = (float*)d_out;

    cudaFuncSetAttribute(lc2d_mma_kernel,
                         cudaFuncAttributeMaxDynamicSharedMemorySize, DYN_SMEM);
    lc2d_mma_kernel<<<1024, 256, DYN_SMEM>>>(x, wgt, bias, out);
}

// round 11
// speedup vs baseline: 2.2718x; 1.2213x over previous
#include <cuda_runtime.h>
#include <cuda_bf16.h>
#include <cstdint>

// LocallyConnected2d, Round 8: gmem operand pre-transforms + cp.async staging.
//  xt_kernel: x[b][ci][r][c]        -> X_T[ci][rc][plane][b]   (bf16 hi/lo, 17MB)
//  wt_kernel: W[ci][o][loc][kk]     -> B_T[loc][k][plane][o]   (bf16 hi/lo, 151MB)
//  main:      per-loc GEMM D[64b x 64o] over K=576, staging = cp.async 16B runs,
//             compute path identical to R5-R7 (ldmatrix.x4.trans + mma bf16 3-pass).

#define VSTRIDE 11520                 // one operand version: 80 rows x 144 B
#define DYN_SMEM (512 + 8 * VSTRIDE)  // bias + {AH,AL,BH,BL} x 2 buffers

__device__ __nv_bfloat16 X_T[(size_t)64 * 1024 * 2 * 64];    // 16.8 MB
__device__ __nv_bfloat16 B_T[(size_t)1024 * 576 * 2 * 64];   // 151 MB

static __device__ __forceinline__ uint32_t s2u(const void* p) {
    uint32_t a;
    asm("{ .reg .u64 t; cvta.to.shared.u64 t, %1; cvt.u32.u64 %0, t; }"
        : "=r"(a) : "l"(p));
    return a;
}

static __device__ __forceinline__ void ldsm4t(uint32_t addr, uint32_t* r) {
    asm volatile("ldmatrix.sync.aligned.m8n8.x4.trans.shared.b16 {%0,%1,%2,%3}, [%4];"
                 : "=r"(r[0]), "=r"(r[1]), "=r"(r[2]), "=r"(r[3]) : "r"(addr));
}

static __device__ __forceinline__ void mma_bf16(float* d, const uint32_t* a,
                                                const uint32_t* b) {
    asm volatile("mma.sync.aligned.m16n8k16.row.col.f32.bf16.bf16.f32 "
                 "{%0,%1,%2,%3}, {%4,%5,%6,%7}, {%8,%9}, {%0,%1,%2,%3};"
                 : "+f"(d[0]), "+f"(d[1]), "+f"(d[2]), "+f"(d[3])
                 : "r"(a[0]), "r"(a[1]), "r"(a[2]), "r"(a[3]),
                   "r"(b[0]), "r"(b[1]));
}

static __device__ __forceinline__ uint32_t hilo_pack(float v0, float v1, int plane) {
    __nv_bfloat16 h0 = __float2bfloat16(v0), h1 = __float2bfloat16(v1);
    __nv_bfloat16 e0, e1;
    if (plane == 0) { e0 = h0; e1 = h1; }
    else {
        e0 = __float2bfloat16(v0 - __bfloat162float(h0));
        e1 = __float2bfloat16(v1 - __bfloat162float(h1));
    }
    return (uint32_t)*(uint16_t*)&e0 | ((uint32_t)*(uint16_t*)&e1 << 16);
}

// ---- x transform: [b][ci][rc] f32 -> X_T[ci][rc][plane][b] bf16 ----
__global__ __launch_bounds__(256)
void xt_kernel(const float* __restrict__ x)
{
    __shared__ float tile[64][129];
    const int ci  = blockIdx.x >> 3;
    const int rc0 = (blockIdx.x & 7) * 128;
    const int tid = threadIdx.x;
    #pragma unroll
    for (int i = 0; i < 32; i++) {
        int q = tid + 256 * i;
        int b = q >> 7, rc = q & 127;
        tile[b][rc] = x[(size_t)b * 65536 + ci * 1024 + rc0 + rc];
    }
    __syncthreads();
    #pragma unroll
    for (int i = 0; i < 32; i++) {
        int q = tid + 256 * i;
        int row = q >> 6, rem = q & 63;
        int plane = rem >> 5, lp = rem & 31;
        uint32_t pk = hilo_pack(tile[2 * lp][row], tile[2 * lp + 1][row], plane);
        *(uint32_t*)&X_T[(((size_t)ci * 1024 + rc0 + row) * 2 + plane) * 64 + 2 * lp] = pk;
    }
}

// ---- W transform: [ci][o][loc][kk] f32 -> B_T[loc][ci*9+kk][plane][o] bf16 ----
__global__ __launch_bounds__(256)
void wt_kernel(const float* __restrict__ wgt)
{
    __shared__ float tile[32][289];
    const int ci  = blockIdx.x >> 6;
    const int o0  = ((blockIdx.x >> 5) & 1) * 32;
    const int loc0 = (blockIdx.x & 31) * 32;
    const int tid = threadIdx.x;
    #pragma unroll
    for (int i = 0; i < 36; i++) {
        int q = tid + 256 * i;
        int o = q / 288, j = q % 288;          // j = loc_l*9 + kk, contiguous
        tile[o][j] = wgt[(size_t)(ci * 64 + o0 + o) * 9216 + loc0 * 9 + j];
    }
    __syncthreads();
    #pragma unroll
    for (int i = 0; i < 36; i++) {
        int q = tid + 256 * i;
        int row = q >> 5, rem = q & 31;        // row 0..287 = (loc_l, kk)
        int plane = rem >> 4, lp = rem & 15;   // lp covers 2 o's
        uint32_t pk = hilo_pack(tile[2 * lp][row], tile[2 * lp + 1][row], plane);
        const int loc = loc0 + row / 9;
        const int k   = ci * 9 + row % 9;
        *(uint32_t*)&B_T[(((size_t)loc * 576 + k) * 2 + plane) * 64 + o0 + 2 * lp] = pk;
    }
}

// ---- main GEMM kernel ----
__global__ __launch_bounds__(256, 2)
void lc2d_mma_kernel(const float* __restrict__ bias, float* __restrict__ out)
{
    extern __shared__ char sm[];
    const uint32_t sb = s2u(sm);
    const int tid  = threadIdx.x;
    const int wid  = tid >> 5;
    const int lane = tid & 31;
    const int h = blockIdx.x >> 5;
    const int w = blockIdx.x & 31;
    const int loc = h * 32 + w;

    float* biasS = (float*)sm;
    if (tid < 64) biasS[tid] = bias[tid * 1024 + loc];

    // Zero pad rows k=72..79 of all 8 operand versions (never overwritten).
    for (int q = tid; q < 2304; q += 256) {
        const int vi = q / 288, rr = q % 288;
        *(float*)(sm + 512 + vi * VSTRIDE + (72 + rr / 36) * 144 + (rr % 36) * 4) = 0.f;
    }

    // cp.async staging: 2304 16B ops per chunk (A/B x hi/lo x 72 k-rows x 8 frags)
    auto stage = [&](int chunk, int buf) {
        const uint32_t vb = sb + 512 + (uint32_t)buf * 4 * VSTRIDE;
        #pragma unroll
        for (int i = 0; i < 9; i++) {
            const int op = tid + 256 * i;
            const int frag = op & 7;
            const int seg = op >> 3;           // 0..287
            const int operand = seg / 144;
            const int rr = seg % 144;
            const int plane = rr / 72;
            const int k = rr % 72;
            const __nv_bfloat16* src;
            uint32_t dst;
            int sz = 16;
            if (operand == 0) {
                const int ci = chunk * 8 + k / 9;
                const int t9 = k % 9;
                int r = h - 1 + t9 / 3;
                int c = w - 1 + t9 % 3;
                if ((unsigned)r >= 32u || (unsigned)c >= 32u) { sz = 0; r = 0; c = 0; }
                src = X_T + ((((size_t)ci * 1024 + r * 32 + c) * 2 + plane) * 64 + frag * 8);
                dst = vb + (uint32_t)(plane * VSTRIDE + k * 144 + frag * 16);
            } else {
                const int kg = chunk * 72 + k;
                src = B_T + ((((size_t)loc * 576 + kg) * 2 + plane) * 64 + frag * 8);
                dst = vb + (uint32_t)((2 + plane) * VSTRIDE + k * 144 + frag * 16);
            }
            asm volatile("cp.async.cg.shared.global [%0], [%1], 16, %2;"
                         :: "r"(dst), "l"(src), "r"(sz) : "memory");
        }
    };

    // ldmatrix.x4.trans lane geometry (verified R5-R7).
    const int blk = lane >> 3, rin = lane & 7;
    const uint32_t aoff = (uint32_t)(((blk >> 1) * 8 + rin) * 144 + ((blk & 1) * 8) * 2);
    const uint32_t boff = (uint32_t)(((blk & 1) * 8 + rin) * 144 + ((blk >> 1) * 8) * 2);
    const int wm = (wid >> 2) * 32;   // warp M base
    const int wn = (wid & 3) * 16;    // warp N base

    float acc[2][2][4];
    #pragma unroll
    for (int i = 0; i < 2; i++)
        #pragma unroll
        for (int j = 0; j < 2; j++)
            #pragma unroll
            for (int k = 0; k < 4; k++)
                acc[i][j][k] = 0.f;

    stage(0, 0);
    asm volatile("cp.async.commit_group;" ::: "memory");

    for (int c = 0; c < 8; c++) {
        if (c < 7) {
            stage(c + 1, (c + 1) & 1);
            asm volatile("cp.async.commit_group;" ::: "memory");
            asm volatile("cp.async.wait_group 1;" ::: "memory");
        } else {
            asm volatile("cp.async.wait_group 0;" ::: "memory");
        }
        __syncthreads();

        const uint32_t vb = sb + 512 + (uint32_t)(c & 1) * 4 * VSTRIDE;
        const uint32_t AH = vb, AL = vb + VSTRIDE;
        const uint32_t BH = vb + 2 * VSTRIDE, BL = vb + 3 * VSTRIDE;

        #pragma unroll
        for (int ks = 0; ks < 5; ks++) {
            const uint32_t kb = (uint32_t)(ks * 16 * 144);
            uint32_t ah[2][4], al[2][4], bh[4], bl[4];
            #pragma unroll
            for (int mt = 0; mt < 2; mt++) {
                const uint32_t ad = kb + aoff + (uint32_t)((wm + mt * 16) * 2);
                ldsm4t(AH + ad, ah[mt]);
                ldsm4t(AL + ad, al[mt]);
            }
            {
                const uint32_t bd = kb + boff + (uint32_t)(wn * 2);
                ldsm4t(BH + bd, bh);
                ldsm4t(BL + bd, bl);
            }
            #pragma unroll
            for (int mt = 0; mt < 2; mt++)
                #pragma unroll
                for (int nt = 0; nt < 2; nt++) {
                    const uint32_t* B2h = &bh[nt * 2];
                    const uint32_t* B2l = &bl[nt * 2];
                    mma_bf16(acc[mt][nt], ah[mt], B2h);   // hi*hi
                    mma_bf16(acc[mt][nt], ah[mt], B2l);   // hi*lo
                    mma_bf16(acc[mt][nt], al[mt], B2h);   // lo*hi
                }
        }
        __syncthreads();
    }

    // Epilogue: frag c0:(g,2t2) c1:(g,2t2+1) c2:(g+8,2t2) c3:(g+8,2t2+1).
    const int g = lane >> 2, t2 = lane & 3;
    #pragma unroll
    for (int mt = 0; mt < 2; mt++)
        #pragma unroll
        for (int nt = 0; nt < 2; nt++)
            #pragma unroll
            for (int cc = 0; cc < 4; cc++) {
                const int b = wm + mt * 16 + g + (cc >> 1) * 8;
                const int o = wn + nt * 8 + t2 * 2 + (cc & 1);
                out[((size_t)(b * 64 + o) << 10) + loc] =
                    acc[mt][nt][cc] + biasS[o];
            }
}

extern "C" void kernel_launch(void* const* d_in, const int* in_sizes, int n_in,
                              void* d_out, int out_size)
{
    const float* x    = (const float*)d_in[0];
    const float* wgt  = (const float*)d_in[1];
    const float* bias = (const float*)d_in[2];
    float* out        = (float*)d_out;

    cudaFuncSetAttribute(lc2d_mma_kernel,
                         cudaFuncAttributeMaxDynamicSharedMemorySize, DYN_SMEM);

    xt_kernel<<<512, 256>>>(x);
    wt_kernel<<<4096, 256>>>(wgt);
    lc2d_mma_kernel<<<1024, 256, DYN_SMEM>>>(bias, out);
}

// round 12
// speedup vs baseline: 2.7696x; 1.2191x over previous
#include <cuda_runtime.h>
#include <cuda_fp16.h>
#include <cstdint>

// LocallyConnected2d, Round 9: fp16 2-pass scheme.
//  A (x patches): fp16 hi+lo planes (a = ah+al exactly, to fp16 precision^2)
//  B (weights):   fp16 hi plane only  -> error only from B rounding (~2^-11)
//  D = (ah+al)*bh accumulated in fp32 via 2 mma passes.
//  xt_kernel: x[b][ci][rc] -> X_T[ci][rc][plane][b]  (17MB)
//  wt_kernel: W[ci][o][loc][kk] -> B_T[loc][k][o]    (75.5MB)
//  main: per-loc GEMM, cp.async 16B staging, 3 CTAs/SM (68KB smem).

#define VSTRIDE 11520                 // one operand version: 80 rows x 144 B
#define DYN_SMEM (512 + 6 * VSTRIDE)  // bias + {AH,AL,BH} x 2 buffers

__device__ __half X_T[(size_t)64 * 1024 * 2 * 64];   // 16.8 MB
__device__ __half B_T[(size_t)1024 * 576 * 64];      // 75.5 MB

static __device__ __forceinline__ uint32_t s2u(const void* p) {
    uint32_t a;
    asm("{ .reg .u64 t; cvta.to.shared.u64 t, %1; cvt.u32.u64 %0, t; }"
        : "=r"(a) : "l"(p));
    return a;
}

static __device__ __forceinline__ void ldsm4t(uint32_t addr, uint32_t* r) {
    asm volatile("ldmatrix.sync.aligned.m8n8.x4.trans.shared.b16 {%0,%1,%2,%3}, [%4];"
                 : "=r"(r[0]), "=r"(r[1]), "=r"(r[2]), "=r"(r[3]) : "r"(addr));
}

static __device__ __forceinline__ void mma_f16(float* d, const uint32_t* a,
                                               const uint32_t* b) {
    asm volatile("mma.sync.aligned.m16n8k16.row.col.f32.f16.f16.f32 "
                 "{%0,%1,%2,%3}, {%4,%5,%6,%7}, {%8,%9}, {%0,%1,%2,%3};"
                 : "+f"(d[0]), "+f"(d[1]), "+f"(d[2]), "+f"(d[3])
                 : "r"(a[0]), "r"(a[1]), "r"(a[2]), "r"(a[3]),
                   "r"(b[0]), "r"(b[1]));
}

static __device__ __forceinline__ uint32_t pack_plane(float v0, float v1, int plane) {
    __half h0 = __float2half_rn(v0), h1 = __float2half_rn(v1);
    __half e0, e1;
    if (plane == 0) { e0 = h0; e1 = h1; }
    else {
        e0 = __float2half_rn(v0 - __half2float(h0));
        e1 = __float2half_rn(v1 - __half2float(h1));
    }
    return (uint32_t)*(uint16_t*)&e0 | ((uint32_t)*(uint16_t*)&e1 << 16);
}

// ---- x transform: [b][ci][rc] f32 -> X_T[ci][rc][plane][b] fp16 ----
__global__ __launch_bounds__(256)
void xt_kernel(const float* __restrict__ x)
{
    __shared__ float tile[64][129];
    const int ci  = blockIdx.x >> 3;
    const int rc0 = (blockIdx.x & 7) * 128;
    const int tid = threadIdx.x;
    #pragma unroll
    for (int i = 0; i < 32; i++) {
        int q = tid + 256 * i;
        int b = q >> 7, rc = q & 127;
        tile[b][rc] = x[(size_t)b * 65536 + ci * 1024 + rc0 + rc];
    }
    __syncthreads();
    #pragma unroll
    for (int i = 0; i < 32; i++) {
        int q = tid + 256 * i;
        int row = q >> 6, rem = q & 63;
        int plane = rem >> 5, lp = rem & 31;
        uint32_t pk = pack_plane(tile[2 * lp][row], tile[2 * lp + 1][row], plane);
        *(uint32_t*)&X_T[(((size_t)ci * 1024 + rc0 + row) * 2 + plane) * 64 + 2 * lp] = pk;
    }
}

// ---- W transform: [ci][o][loc][kk] f32 -> B_T[loc][ci*9+kk][o] fp16 (hi only) ----
__global__ __launch_bounds__(256)
void wt_kernel(const float* __restrict__ wgt)
{
    __shared__ float tile[32][289];
    const int ci   = blockIdx.x >> 6;
    const int o0   = ((blockIdx.x >> 5) & 1) * 32;
    const int loc0 = (blockIdx.x & 31) * 32;
    const int tid  = threadIdx.x;
    #pragma unroll
    for (int i = 0; i < 36; i++) {
        int q = tid + 256 * i;
        int o = q / 288, j = q % 288;          // j = loc_l*9 + kk (contiguous)
        tile[o][j] = wgt[(size_t)(ci * 64 + o0 + o) * 9216 + loc0 * 9 + j];
    }
    __syncthreads();
    #pragma unroll
    for (int i = 0; i < 18; i++) {
        int q = tid + 256 * i;                 // 4608 units: 288 rows x 16 lp
        int row = q >> 4, lp = q & 15;         // lp covers 2 o's
        uint32_t pk = pack_plane(tile[2 * lp][row], tile[2 * lp + 1][row], 0);
        const int loc = loc0 + row / 9;
        const int k   = ci * 9 + row % 9;
        *(uint32_t*)&B_T[((size_t)loc * 576 + k) * 64 + o0 + 2 * lp] = pk;
    }
}

// ---- main GEMM kernel ----
__global__ __launch_bounds__(256, 3)
void lc2d_mma_kernel(const float* __restrict__ bias, float* __restrict__ out)
{
    extern __shared__ char sm[];
    const uint32_t sb = s2u(sm);
    const int tid  = threadIdx.x;
    const int wid  = tid >> 5;
    const int lane = tid & 31;
    const int h = blockIdx.x >> 5;
    const int w = blockIdx.x & 31;
    const int loc = h * 32 + w;

    float* biasS = (float*)sm;
    if (tid < 64) biasS[tid] = bias[tid * 1024 + loc];

    // Zero pad rows k=72..79 of all 6 operand versions (never overwritten).
    for (int q = tid; q < 1728; q += 256) {
        const int vi = q / 288, rr = q % 288;
        *(float*)(sm + 512 + vi * VSTRIDE + (72 + rr / 36) * 144 + (rr % 36) * 4) = 0.f;
    }

    // cp.async staging: 1728 16B ops per chunk ({A-hi,A-lo,B-hi} x 72 k x 8 frags)
    auto stage = [&](int chunk, int buf) {
        const uint32_t vb = sb + 512 + (uint32_t)buf * 3 * VSTRIDE;
        #pragma unroll
        for (int i = 0; i < 7; i++) {
            const int op = tid + 256 * i;
            if (op >= 1728) break;
            const int frag = op & 7;
            const int seg = op >> 3;           // 0..215
            const __half* src;
            uint32_t dst;
            int sz = 16;
            if (seg < 144) {                   // A planes
                const int plane = seg / 72;
                const int k = seg % 72;
                const int ci = chunk * 8 + k / 9;
                const int t9 = k % 9;
                int r = h - 1 + t9 / 3;
                int c = w - 1 + t9 % 3;
                if ((unsigned)r >= 32u || (unsigned)c >= 32u) { sz = 0; r = 0; c = 0; }
                src = X_T + ((((size_t)ci * 1024 + r * 32 + c) * 2 + plane) * 64 + frag * 8);
                dst = vb + (uint32_t)(plane * VSTRIDE + k * 144 + frag * 16);
            } else {                           // B hi
                const int k = seg - 144;
                const int kg = chunk * 72 + k;
                src = B_T + (((size_t)loc * 576 + kg) * 64 + frag * 8);
                dst = vb + (uint32_t)(2 * VSTRIDE + k * 144 + frag * 16);
            }
            asm volatile("cp.async.cg.shared.global [%0], [%1], 16, %2;"
                         :: "r"(dst), "l"(src), "r"(sz) : "memory");
        }
    };

    // ldmatrix.x4.trans lane geometry (verified R5-R8).
    const int blk = lane >> 3, rin = lane & 7;
    const uint32_t aoff = (uint32_t)(((blk >> 1) * 8 + rin) * 144 + ((blk & 1) * 8) * 2);
    const uint32_t boff = (uint32_t)(((blk & 1) * 8 + rin) * 144 + ((blk >> 1) * 8) * 2);
    const int wm = (wid >> 2) * 32;   // warp M base
    const int wn = (wid & 3) * 16;    // warp N base

    float acc[2][2][4];
    #pragma unroll
    for (int i = 0; i < 2; i++)
        #pragma unroll
        for (int j = 0; j < 2; j++)
            #pragma unroll
            for (int k = 0; k < 4; k++)
                acc[i][j][k] = 0.f;

    stage(0, 0);
    asm volatile("cp.async.commit_group;" ::: "memory");

    for (int c = 0; c < 8; c++) {
        if (c < 7) {
            stage(c + 1, (c + 1) & 1);
            asm volatile("cp.async.commit_group;" ::: "memory");
            asm volatile("cp.async.wait_group 1;" ::: "memory");
        } else {
            asm volatile("cp.async.wait_group 0;" ::: "memory");
        }
        __syncthreads();

        const uint32_t vb = sb + 512 + (uint32_t)(c & 1) * 3 * VSTRIDE;
        const uint32_t AH = vb, AL = vb + VSTRIDE, BH = vb + 2 * VSTRIDE;

        #pragma unroll
        for (int ks = 0; ks < 5; ks++) {
            const uint32_t kb = (uint32_t)(ks * 16 * 144);
            uint32_t ah[2][4], al[2][4], bh[4];
            #pragma unroll
            for (int mt = 0; mt < 2; mt++) {
                const uint32_t ad = kb + aoff + (uint32_t)((wm + mt * 16) * 2);
                ldsm4t(AH + ad, ah[mt]);
                ldsm4t(AL + ad, al[mt]);
            }
            {
                const uint32_t bd = kb + boff + (uint32_t)(wn * 2);
                ldsm4t(BH + bd, bh);
            }
            #pragma unroll
            for (int mt = 0; mt < 2; mt++)
                #pragma unroll
                for (int nt = 0; nt < 2; nt++) {
                    const uint32_t* B2 = &bh[nt * 2];
                    mma_f16(acc[mt][nt], ah[mt], B2);   // ah*bh
                    mma_f16(acc[mt][nt], al[mt], B2);   // al*bh
                }
        }
        __syncthreads();
    }

    // Epilogue: frag c0:(g,2t2) c1:(g,2t2+1) c2:(g+8,2t2) c3:(g+8,2t2+1).
    const int g = lane >> 2, t2 = lane & 3;
    #pragma unroll
    for (int mt = 0; mt < 2; mt++)
        #pragma unroll
        for (int nt = 0; nt < 2; nt++)
            #pragma unroll
            for (int cc = 0; cc < 4; cc++) {
                const int b = wm + mt * 16 + g + (cc >> 1) * 8;
                const int o = wn + nt * 8 + t2 * 2 + (cc & 1);
                out[((size_t)(b * 64 + o) << 10) + loc] =
                    acc[mt][nt][cc] + biasS[o];
            }
}

extern "C" void kernel_launch(void* const* d_in, const int* in_sizes, int n_in,
                              void* d_out, int out_size)
{
    const float* x    = (const float*)d_in[0];
    const float* wgt  = (const float*)d_in[1];
    const float* bias = (const float*)d_in[2];
    float* out        = (float*)d_out;

    cudaFuncSetAttribute(lc2d_mma_kernel,
                         cudaFuncAttributeMaxDynamicSharedMemorySize, DYN_SMEM);

    xt_kernel<<<512, 256>>>(x);
    wt_kernel<<<4096, 256>>>(wgt);
    lc2d_mma_kernel<<<1024, 256, DYN_SMEM>>>(bias, out);
}

// round 13
// speedup vs baseline: 3.2217x; 1.1632x over previous
#include <cuda_runtime.h>
#include <cuda_fp16.h>
#include <cstdint>

// LocallyConnected2d, Round 10: R9 (fp16 2-pass, cp.async staging) + epilogue fix.
//  Main kernel now stores coalesced to OUT_T[loc][b*64+o]; new ot_kernel does a
//  clean 1024x4096 transpose to out[b][o][loc]. Kills the 8x L2 sector
//  amplification of per-loc scattered 4B stores.

#define VSTRIDE 11520                 // one operand version: 80 rows x 144 B
#define DYN_SMEM (512 + 6 * VSTRIDE)  // bias + {AH,AL,BH} x 2 buffers

__device__ __half X_T[(size_t)64 * 1024 * 2 * 64];   // 16.8 MB
__device__ __half B_T[(size_t)1024 * 576 * 64];      // 75.5 MB
__device__ float  OUT_T[(size_t)1024 * 4096];        // 16.8 MB  [loc][b*64+o]

static __device__ __forceinline__ uint32_t s2u(const void* p) {
    uint32_t a;
    asm("{ .reg .u64 t; cvta.to.shared.u64 t, %1; cvt.u32.u64 %0, t; }"
        : "=r"(a) : "l"(p));
    return a;
}

static __device__ __forceinline__ void ldsm4t(uint32_t addr, uint32_t* r) {
    asm volatile("ldmatrix.sync.aligned.m8n8.x4.trans.shared.b16 {%0,%1,%2,%3}, [%4];"
                 : "=r"(r[0]), "=r"(r[1]), "=r"(r[2]), "=r"(r[3]) : "r"(addr));
}

static __device__ __forceinline__ void mma_f16(float* d, const uint32_t* a,
                                               const uint32_t* b) {
    asm volatile("mma.sync.aligned.m16n8k16.row.col.f32.f16.f16.f32 "
                 "{%0,%1,%2,%3}, {%4,%5,%6,%7}, {%8,%9}, {%0,%1,%2,%3};"
                 : "+f"(d[0]), "+f"(d[1]), "+f"(d[2]), "+f"(d[3])
                 : "r"(a[0]), "r"(a[1]), "r"(a[2]), "r"(a[3]),
                   "r"(b[0]), "r"(b[1]));
}

static __device__ __forceinline__ uint32_t pack_plane(float v0, float v1, int plane) {
    __half h0 = __float2half_rn(v0), h1 = __float2half_rn(v1);
    __half e0, e1;
    if (plane == 0) { e0 = h0; e1 = h1; }
    else {
        e0 = __float2half_rn(v0 - __half2float(h0));
        e1 = __float2half_rn(v1 - __half2float(h1));
    }
    return (uint32_t)*(uint16_t*)&e0 | ((uint32_t)*(uint16_t*)&e1 << 16);
}

// ---- x transform: [b][ci][rc] f32 -> X_T[ci][rc][plane][b] fp16 ----
__global__ __launch_bounds__(256)
void xt_kernel(const float* __restrict__ x)
{
    __shared__ float tile[64][129];
    const int ci  = blockIdx.x >> 3;
    const int rc0 = (blockIdx.x & 7) * 128;
    const int tid = threadIdx.x;
    #pragma unroll
    for (int i = 0; i < 32; i++) {
        int q = tid + 256 * i;
        int b = q >> 7, rc = q & 127;
        tile[b][rc] = x[(size_t)b * 65536 + ci * 1024 + rc0 + rc];
    }
    __syncthreads();
    #pragma unroll
    for (int i = 0; i < 32; i++) {
        int q = tid + 256 * i;
        int row = q >> 6, rem = q & 63;
        int plane = rem >> 5, lp = rem & 31;
        uint32_t pk = pack_plane(tile[2 * lp][row], tile[2 * lp + 1][row], plane);
        *(uint32_t*)&X_T[(((size_t)ci * 1024 + rc0 + row) * 2 + plane) * 64 + 2 * lp] = pk;
    }
}

// ---- W transform: [ci][o][loc][kk] f32 -> B_T[loc][ci*9+kk][o] fp16 ----
__global__ __launch_bounds__(256)
void wt_kernel(const float* __restrict__ wgt)
{
    __shared__ float tile[32][289];
    const int ci   = blockIdx.x >> 6;
    const int o0   = ((blockIdx.x >> 5) & 1) * 32;
    const int loc0 = (blockIdx.x & 31) * 32;
    const int tid  = threadIdx.x;
    #pragma unroll
    for (int i = 0; i < 36; i++) {
        int q = tid + 256 * i;
        int o = q / 288, j = q % 288;          // j = loc_l*9 + kk (contiguous)
        tile[o][j] = wgt[(size_t)(ci * 64 + o0 + o) * 9216 + loc0 * 9 + j];
    }
    __syncthreads();
    #pragma unroll
    for (int i = 0; i < 18; i++) {
        int q = tid + 256 * i;                 // 4608 units: 288 rows x 16 lp
        int row = q >> 4, lp = q & 15;
        uint32_t pk = pack_plane(tile[2 * lp][row], tile[2 * lp + 1][row], 0);
        const int loc = loc0 + row / 9;
        const int k   = ci * 9 + row % 9;
        *(uint32_t*)&B_T[((size_t)loc * 576 + k) * 64 + o0 + 2 * lp] = pk;
    }
}

// ---- output transpose: OUT_T[loc][bo] -> out[bo][loc], both sides coalesced ----
__global__ __launch_bounds__(256)
void ot_kernel(float* __restrict__ out)
{
    __shared__ float tile[32][33];
    const int bo0  = (blockIdx.x & 127) * 32;
    const int loc0 = (blockIdx.x >> 7) * 32;
    const int tid  = threadIdx.x;
    const int rl   = tid >> 5, cl = tid & 31;
    #pragma unroll
    for (int i = 0; i < 4; i++)
        tile[rl + i * 8][cl] = OUT_T[(size_t)(loc0 + rl + i * 8) * 4096 + bo0 + cl];
    __syncthreads();
    #pragma unroll
    for (int i = 0; i < 4; i++)
        out[(size_t)(bo0 + rl + i * 8) * 1024 + loc0 + cl] = tile[cl][rl + i * 8];
}

// ---- main GEMM kernel ----
__global__ __launch_bounds__(256, 3)
void lc2d_mma_kernel(const float* __restrict__ bias)
{
    extern __shared__ char sm[];
    const uint32_t sb = s2u(sm);
    const int tid  = threadIdx.x;
    const int wid  = tid >> 5;
    const int lane = tid & 31;
    const int h = blockIdx.x >> 5;
    const int w = blockIdx.x & 31;
    const int loc = h * 32 + w;

    float* biasS = (float*)sm;
    if (tid < 64) biasS[tid] = bias[tid * 1024 + loc];

    // Zero pad rows k=72..79 of all 6 operand versions (never overwritten).
    for (int q = tid; q < 1728; q += 256) {
        const int vi = q / 288, rr = q % 288;
        *(float*)(sm + 512 + vi * VSTRIDE + (72 + rr / 36) * 144 + (rr % 36) * 4) = 0.f;
    }

    // cp.async staging: 1728 16B ops per chunk ({A-hi,A-lo,B-hi} x 72 k x 8 frags)
    auto stage = [&](int chunk, int buf) {
        const uint32_t vb = sb + 512 + (uint32_t)buf * 3 * VSTRIDE;
        #pragma unroll
        for (int i = 0; i < 7; i++) {
            const int op = tid + 256 * i;
            if (op >= 1728) break;
            const int frag = op & 7;
            const int seg = op >> 3;           // 0..215
            const __half* src;
            uint32_t dst;
            int sz = 16;
            if (seg < 144) {                   // A planes
                const int plane = seg / 72;
                const int k = seg % 72;
                const int ci = chunk * 8 + k / 9;
                const int t9 = k % 9;
                int r = h - 1 + t9 / 3;
                int c = w - 1 + t9 % 3;
                if ((unsigned)r >= 32u || (unsigned)c >= 32u) { sz = 0; r = 0; c = 0; }
                src = X_T + ((((size_t)ci * 1024 + r * 32 + c) * 2 + plane) * 64 + frag * 8);
                dst = vb + (uint32_t)(plane * VSTRIDE + k * 144 + frag * 16);
            } else {                           // B hi
                const int k = seg - 144;
                const int kg = chunk * 72 + k;
                src = B_T + (((size_t)loc * 576 + kg) * 64 + frag * 8);
                dst = vb + (uint32_t)(2 * VSTRIDE + k * 144 + frag * 16);
            }
            asm volatile("cp.async.cg.shared.global [%0], [%1], 16, %2;"
                         :: "r"(dst), "l"(src), "r"(sz) : "memory");
        }
    };

    // ldmatrix.x4.trans lane geometry (verified R5-R9).
    const int blk = lane >> 3, rin = lane & 7;
    const uint32_t aoff = (uint32_t)(((blk >> 1) * 8 + rin) * 144 + ((blk & 1) * 8) * 2);
    const uint32_t boff = (uint32_t)(((blk & 1) * 8 + rin) * 144 + ((blk >> 1) * 8) * 2);
    const int wm = (wid >> 2) * 32;   // warp M base
    const int wn = (wid & 3) * 16;    // warp N base

    float acc[2][2][4];
    #pragma unroll
    for (int i = 0; i < 2; i++)
        #pragma unroll
        for (int j = 0; j < 2; j++)
            #pragma unroll
            for (int k = 0; k < 4; k++)
                acc[i][j][k] = 0.f;

    stage(0, 0);
    asm volatile("cp.async.commit_group;" ::: "memory");

    for (int c = 0; c < 8; c++) {
        if (c < 7) {
            stage(c + 1, (c + 1) & 1);
            asm volatile("cp.async.commit_group;" ::: "memory");
            asm volatile("cp.async.wait_group 1;" ::: "memory");
        } else {
            asm volatile("cp.async.wait_group 0;" ::: "memory");
        }
        __syncthreads();

        const uint32_t vb = sb + 512 + (uint32_t)(c & 1) * 3 * VSTRIDE;
        const uint32_t AH = vb, AL = vb + VSTRIDE, BH = vb + 2 * VSTRIDE;

        #pragma unroll
        for (int ks = 0; ks < 5; ks++) {
            const uint32_t kb = (uint32_t)(ks * 16 * 144);
            uint32_t ah[2][4], al[2][4], bh[4];
            #pragma unroll
            for (int mt = 0; mt < 2; mt++) {
                const uint32_t ad = kb + aoff + (uint32_t)((wm + mt * 16) * 2);
                ldsm4t(AH + ad, ah[mt]);
                ldsm4t(AL + ad, al[mt]);
            }
            {
                const uint32_t bd = kb + boff + (uint32_t)(wn * 2);
                ldsm4t(BH + bd, bh);
            }
            #pragma unroll
            for (int mt = 0; mt < 2; mt++)
                #pragma unroll
                for (int nt = 0; nt < 2; nt++) {
                    const uint32_t* B2 = &bh[nt * 2];
                    mma_f16(acc[mt][nt], ah[mt], B2);   // ah*bh
                    mma_f16(acc[mt][nt], al[mt], B2);   // al*bh
                }
        }
        __syncthreads();
    }

    // Epilogue: coalesced STG.64 into OUT_T[loc][b*64+o].
    // Frag: c0:(g,2t2) c1:(g,2t2+1) c2:(g+8,2t2) c3:(g+8,2t2+1).
    const int g = lane >> 2, t2 = lane & 3;
    float* ob = OUT_T + (size_t)loc * 4096;
    #pragma unroll
    for (int mt = 0; mt < 2; mt++)
        #pragma unroll
        for (int nt = 0; nt < 2; nt++)
            #pragma unroll
            for (int rp = 0; rp < 2; rp++) {
                const int b = wm + mt * 16 + g + rp * 8;
                const int o = wn + nt * 8 + t2 * 2;
                float2 v;
                v.x = acc[mt][nt][rp * 2 + 0] + biasS[o];
                v.y = acc[mt][nt][rp * 2 + 1] + biasS[o + 1];
                *(float2*)(ob + b * 64 + o) = v;
            }
}

extern "C" void kernel_launch(void* const* d_in, const int* in_sizes, int n_in,
                              void* d_out, int out_size)
{
    const float* x    = (const float*)d_in[0];
    const float* wgt  = (const float*)d_in[1];
    const float* bias = (const float*)d_in[2];
    float* out        = (float*)d_out;

    cudaFuncSetAttribute(lc2d_mma_kernel,
                         cudaFuncAttributeMaxDynamicSharedMemorySize, DYN_SMEM);

    xt_kernel<<<512, 256>>>(x);
    wt_kernel<<<4096, 256>>>(wgt);
    lc2d_mma_kernel<<<1024, 256, DYN_SMEM>>>(bias);
    ot_kernel<<<4096, 256>>>(out);
}

// round 15
// speedup vs baseline: 4.5504x; 1.4124x over previous
#include <cuda_runtime.h>
#include <cuda_fp16.h>
#include <cstdint>

// LocallyConnected2d, Round 11: fp16 single-plane A + single-plane B.
//  Error sources: fp16 rounding of A and of B (~2^-11 each, independent) ->
//  rel_err ~3e-4, under the 1e-3 gate. Halves mma count, cuts staging 33%,
//  smem 46KB -> 4 CTAs/SM.
//  xt: x[b][ci][rc] -> X_T[ci][rc][b] fp16 (8.4MB)
//  wt: W[ci][o][loc][kk] -> B_T[loc][ci*9+kk][o] fp16 (75.5MB), float4 loads
//  main: per-loc GEMM D[64b x 64o], cp.async staging, coalesced OUT_T store
//  ot: OUT_T[loc][bo] -> out[bo][loc] transpose

#define VSTRIDE 11520                 // one operand version: 80 rows x 144 B
#define DYN_SMEM (512 + 4 * VSTRIDE)  // bias + {AH,BH} x 2 buffers = 46592 B

__device__ __half X_T[(size_t)64 * 1024 * 64];       // 8.4 MB
__device__ __half B_T[(size_t)1024 * 576 * 64];      // 75.5 MB
__device__ float  OUT_T[(size_t)1024 * 4096];        // 16.8 MB  [loc][b*64+o]

static __device__ __forceinline__ uint32_t s2u(const void* p) {
    uint32_t a;
    asm("{ .reg .u64 t; cvta.to.shared.u64 t, %1; cvt.u32.u64 %0, t; }"
        : "=r"(a) : "l"(p));
    return a;
}

static __device__ __forceinline__ void ldsm4t(uint32_t addr, uint32_t* r) {
    asm volatile("ldmatrix.sync.aligned.m8n8.x4.trans.shared.b16 {%0,%1,%2,%3}, [%4];"
                 : "=r"(r[0]), "=r"(r[1]), "=r"(r[2]), "=r"(r[3]) : "r"(addr));
}

static __device__ __forceinline__ void mma_f16(float* d, const uint32_t* a,
                                               const uint32_t* b) {
    asm volatile("mma.sync.aligned.m16n8k16.row.col.f32.f16.f16.f32 "
                 "{%0,%1,%2,%3}, {%4,%5,%6,%7}, {%8,%9}, {%0,%1,%2,%3};"
                 : "+f"(d[0]), "+f"(d[1]), "+f"(d[2]), "+f"(d[3])
                 : "r"(a[0]), "r"(a[1]), "r"(a[2]), "r"(a[3]),
                   "r"(b[0]), "r"(b[1]));
}

static __device__ __forceinline__ uint32_t pack_h2(float v0, float v1) {
    __half h0 = __float2half_rn(v0), h1 = __float2half_rn(v1);
    return (uint32_t)*(uint16_t*)&h0 | ((uint32_t)*(uint16_t*)&h1 << 16);
}

// ---- x transform: [b][ci][rc] f32 -> X_T[ci][rc][b] fp16 ----
__global__ __launch_bounds__(256)
void xt_kernel(const float* __restrict__ x)
{
    __shared__ float tile[64][129];
    const int ci  = blockIdx.x >> 3;
    const int rc0 = (blockIdx.x & 7) * 128;
    const int tid = threadIdx.x;
    #pragma unroll
    for (int i = 0; i < 32; i++) {
        int q = tid + 256 * i;
        int b = q >> 7, rc = q & 127;
        tile[b][rc] = x[(size_t)b * 65536 + ci * 1024 + rc0 + rc];
    }
    __syncthreads();
    #pragma unroll
    for (int i = 0; i < 16; i++) {
        int q = tid + 256 * i;                 // 4096: 128 rows x 32 lp
        int row = q >> 5, lp = q & 31;
        uint32_t pk = pack_h2(tile[2 * lp][row], tile[2 * lp + 1][row]);
        *(uint32_t*)&X_T[((size_t)ci * 1024 + rc0 + row) * 64 + 2 * lp] = pk;
    }
}

// ---- W transform: [ci][o][loc][kk] f32 -> B_T[loc][ci*9+kk][o] fp16 ----
__global__ __launch_bounds__(256)
void wt_kernel(const float* __restrict__ wgt)
{
    __shared__ float tile[32][289];
    const int ci   = blockIdx.x >> 6;
    const int o0   = ((blockIdx.x >> 5) & 1) * 32;
    const int loc0 = (blockIdx.x & 31) * 32;
    const int tid  = threadIdx.x;
    // float4 loads: 2304 f4 = 32 o-rows x 72 f4 (288 floats contiguous per row)
    #pragma unroll
    for (int i = 0; i < 9; i++) {
        int q = tid + 256 * i;
        int o = q / 72, j = q % 72;
        float4 v = *(const float4*)(wgt + (size_t)(ci * 64 + o0 + o) * 9216
                                        + loc0 * 9 + 4 * j);
        tile[o][4 * j + 0] = v.x;
        tile[o][4 * j + 1] = v.y;
        tile[o][4 * j + 2] = v.z;
        tile[o][4 * j + 3] = v.w;
    }
    __syncthreads();
    #pragma unroll
    for (int i = 0; i < 18; i++) {
        int q = tid + 256 * i;                 // 4608: 288 rows x 16 lp
        int row = q >> 4, lp = q & 15;
        uint32_t pk = pack_h2(tile[2 * lp][row], tile[2 * lp + 1][row]);
        const int loc = loc0 + row / 9;
        const int k   = ci * 9 + row % 9;
        *(uint32_t*)&B_T[((size_t)loc * 576 + k) * 64 + o0 + 2 * lp] = pk;
    }
}

// ---- output transpose: OUT_T[loc][bo] -> out[bo][loc] ----
__global__ __launch_bounds__(256)
void ot_kernel(float* __restrict__ out)
{
    __shared__ float tile[32][33];
    const int bo0  = (blockIdx.x & 127) * 32;
    const int loc0 = (blockIdx.x >> 7) * 32;
    const int tid  = threadIdx.x;
    const int rl   = tid >> 5, cl = tid & 31;
    #pragma unroll
    for (int i = 0; i < 4; i++)
        tile[rl + i * 8][cl] = OUT_T[(size_t)(loc0 + rl + i * 8) * 4096 + bo0 + cl];
    __syncthreads();
    #pragma unroll
    for (int i = 0; i < 4; i++)
        out[(size_t)(bo0 + rl + i * 8) * 1024 + loc0 + cl] = tile[cl][rl + i * 8];
}

// ---- main GEMM kernel ----
__global__ __launch_bounds__(256, 4)
void lc2d_mma_kernel(const float* __restrict__ bias)
{
    extern __shared__ char sm[];
    const uint32_t sb = s2u(sm);
    const int tid  = threadIdx.x;
    const int wid  = tid >> 5;
    const int lane = tid & 31;
    const int h = blockIdx.x >> 5;
    const int w = blockIdx.x & 31;
    const int loc = h * 32 + w;

    float* biasS = (float*)sm;
    if (tid < 64) biasS[tid] = bias[tid * 1024 + loc];

    // Zero pad rows k=72..79 of all 4 operand versions (never overwritten).
    for (int q = tid; q < 1152; q += 256) {
        const int vi = q / 288, rr = q % 288;
        *(float*)(sm + 512 + vi * VSTRIDE + (72 + rr / 36) * 144 + (rr % 36) * 4) = 0.f;
    }

    // cp.async staging: 1152 16B ops per chunk ({A,B} x 72 k-rows x 8 frags)
    auto stage = [&](int chunk, int buf) {
        const uint32_t vb = sb + 512 + (uint32_t)buf * 2 * VSTRIDE;
        #pragma unroll
        for (int i = 0; i < 5; i++) {
            const int op = tid + 256 * i;
            if (op >= 1152) break;
            const int frag = op & 7;
            const int seg = op >> 3;           // 0..143
            const __half* src;
            uint32_t dst;
            int sz = 16;
            if (seg < 72) {                    // A
                const int k = seg;
                const int ci = chunk * 8 + k / 9;
                const int t9 = k % 9;
                int r = h - 1 + t9 / 3;
                int c = w - 1 + t9 % 3;
                if ((unsigned)r >= 32u || (unsigned)c >= 32u) { sz = 0; r = 0; c = 0; }
                src = X_T + (((size_t)ci * 1024 + r * 32 + c) * 64 + frag * 8);
                dst = vb + (uint32_t)(k * 144 + frag * 16);
            } else {                           // B
                const int k = seg - 72;
                const int kg = chunk * 72 + k;
                src = B_T + (((size_t)loc * 576 + kg) * 64 + frag * 8);
                dst = vb + (uint32_t)(VSTRIDE + k * 144 + frag * 16);
            }
            asm volatile("cp.async.cg.shared.global [%0], [%1], 16, %2;"
                         :: "r"(dst), "l"(src), "r"(sz) : "memory");
        }
    };

    // ldmatrix.x4.trans lane geometry (verified R5-R10).
    const int blk = lane >> 3, rin = lane & 7;
    const uint32_t aoff = (uint32_t)(((blk >> 1) * 8 + rin) * 144 + ((blk & 1) * 8) * 2);
    const uint32_t boff = (uint32_t)(((blk & 1) * 8 + rin) * 144 + ((blk >> 1) * 8) * 2);
    const int wm = (wid >> 2) * 32;   // warp M base
    const int wn = (wid & 3) * 16;    // warp N base

    float acc[2][2][4];
    #pragma unroll
    for (int i = 0; i < 2; i++)
        #pragma unroll
        for (int j = 0; j < 2; j++)
            #pragma unroll
            for (int k = 0; k < 4; k++)
                acc[i][j][k] = 0.f;

    stage(0, 0);
    asm volatile("cp.async.commit_group;" ::: "memory");

    for (int c = 0; c < 8; c++) {
        if (c < 7) {
            stage(c + 1, (c + 1) & 1);
            asm volatile("cp.async.commit_group;" ::: "memory");
            asm volatile("cp.async.wait_group 1;" ::: "memory");
        } else {
            asm volatile("cp.async.wait_group 0;" ::: "memory");
        }
        __syncthreads();

        const uint32_t vb = sb + 512 + (uint32_t)(c & 1) * 2 * VSTRIDE;
        const uint32_t AH = vb, BH = vb + VSTRIDE;

        #pragma unroll
        for (int ks = 0; ks < 5; ks++) {
            const uint32_t kb = (uint32_t)(ks * 16 * 144);
            uint32_t ah[2][4], bh[4];
            #pragma unroll
            for (int mt = 0; mt < 2; mt++)
                ldsm4t(AH + kb + aoff + (uint32_t)((wm + mt * 16) * 2), ah[mt]);
            ldsm4t(BH + kb + boff + (uint32_t)(wn * 2), bh);
            #pragma unroll
            for (int mt = 0; mt < 2; mt++)
                #pragma unroll
                for (int nt = 0; nt < 2; nt++)
                    mma_f16(acc[mt][nt], ah[mt], &bh[nt * 2]);
        }
        __syncthreads();
    }

    // Epilogue: coalesced STG.64 into OUT_T[loc][b*64+o].
    const int g = lane >> 2, t2 = lane & 3;
    float* ob = OUT_T + (size_t)loc * 4096;
    #pragma unroll
    for (int mt = 0; mt < 2; mt++)
        #pragma unroll
        for (int nt = 0; nt < 2; nt++)
            #pragma unroll
            for (int rp = 0; rp < 2; rp++) {
                const int b = wm + mt * 16 + g + rp * 8;
                const int o = wn + nt * 8 + t2 * 2;
                float2 v;
                v.x = acc[mt][nt][rp * 2 + 0] + biasS[o];
                v.y = acc[mt][nt][rp * 2 + 1] + biasS[o + 1];
                *(float2*)(ob + b * 64 + o) = v;
            }
}

extern "C" void kernel_launch(void* const* d_in, const int* in_sizes, int n_in,
                              void* d_out, int out_size)
{
    const float* x    = (const float*)d_in[0];
    const float* wgt  = (const float*)d_in[1];
    const float* bias = (const float*)d_in[2];
    float* out        = (float*)d_out;

    cudaFuncSetAttribute(lc2d_mma_kernel,
                         cudaFuncAttributeMaxDynamicSharedMemorySize, DYN_SMEM);

    xt_kernel<<<512, 256>>>(x);
    wt_kernel<<<4096, 256>>>(wgt);
    lc2d_mma_kernel<<<1024, 256, DYN_SMEM>>>(bias);
    ot_kernel<<<4096, 256>>>(out);
}